// round 1
// baseline (speedup 1.0000x reference)
#include <cuda_runtime.h>

#define NW 16               // warps (= batches) per CTA
#define NTHR 512
#define ALPHA 0.2f
#define BN_EPS 1e-5f

// ---- shared memory layout (float offsets) ----
#define OFF_W1Q 0
#define SZ_W1Q  8192        // 64 k-pairs x 32 lanes x 4 (zero-padded k>=125)
#define OFF_W2Q (OFF_W1Q + SZ_W1Q)      // 8192
#define SZ_W2Q  2048        // 16 quads x 32 lanes x 4
#define OFF_WLS (OFF_W2Q + SZ_W2Q)      // 10240
#define SZ_WLS  4160        // [320][13] transposed
#define OFF_A11 (OFF_WLS + SZ_WLS)      // 14400
#define OFF_A21 (OFF_A11 + 64)          // 14464
#define OFF_A12 (OFF_A21 + 64)          // 14528
#define OFF_A22 (OFF_A12 + 32)          // 14560
#define OFF_SC1 (OFF_A22 + 32)          // 14592
#define OFF_BI1 (OFF_SC1 + 5)
#define OFF_SC2 (OFF_BI1 + 5)
#define OFF_BI2 (OFF_SC2 + 5)
#define OFF_BL  (OFF_BI2 + 5)           // 14612 (13)
#define OFF_WARP 14628                  // 16B aligned
#define PW 1920                         // per-warp: xs 2*5*128 + ysA 320 + ysN 320
#define SMEM_FLOATS (OFF_WARP + NW * PW)
#define SMEM_BYTES (SMEM_FLOATS * 4)    // 181392 B

typedef unsigned long long u64;

__device__ __forceinline__ u64 pk(float a, float b) {
    u64 r; asm("mov.b64 %0, {%1, %2};" : "=l"(r) : "f"(a), "f"(b)); return r;
}
__device__ __forceinline__ float2 upk(u64 v) {
    float2 r; asm("mov.b64 {%0, %1}, %2;" : "=f"(r.x), "=f"(r.y) : "l"(v)); return r;
}
// packed fp32x2 FMA (Blackwell f32x2 pipe): d = a*b + d, two lanes per reg-pair
__device__ __forceinline__ void fma2(u64& d, u64 a, u64 b) {
    asm("fma.rn.f32x2 %0, %1, %2, %3;" : "=l"(d) : "l"(a), "l"(b), "l"(d));
}
__device__ __forceinline__ float wred(float v) {
    #pragma unroll
    for (int s = 16; s > 0; s >>= 1) v += __shfl_xor_sync(0xffffffffu, v, s);
    return v;
}

// e[i][j] = lrelu(s1[i] + s2[j]); attn = softmax over i (axis=1);
// o[c][i] += sum_j attn[i][j] * h[c][j]
template <int C>
__device__ __forceinline__ void attn_apply(const float s1[5], const float s2[5],
                                           const float (&h)[C][5], float (&o)[C][5]) {
    #pragma unroll
    for (int j = 0; j < 5; ++j) {
        float e[5]; float m = -1e30f;
        #pragma unroll
        for (int i = 0; i < 5; ++i) {
            float v = s1[i] + s2[j];
            v = v > 0.f ? v : ALPHA * v;
            e[i] = v; m = fmaxf(m, v);
        }
        float Z = 0.f;
        #pragma unroll
        for (int i = 0; i < 5; ++i) { e[i] = __expf(e[i] - m); Z += e[i]; }
        float r = __fdividef(1.f, Z);
        #pragma unroll
        for (int i = 0; i < 5; ++i) {
            float wv = e[i] * r;
            #pragma unroll
            for (int c = 0; c < C; ++c) o[c][i] = fmaf(wv, h[c][j], o[c][i]);
        }
    }
}

__global__ void __launch_bounds__(NTHR, 1)
gat_kernel(const float* __restrict__ x,
           const float* __restrict__ Wt1, const float* __restrict__ a11, const float* __restrict__ a21,
           const float* __restrict__ g1, const float* __restrict__ b1,
           const float* __restrict__ m1, const float* __restrict__ v1,
           const float* __restrict__ Wt2, const float* __restrict__ a12, const float* __restrict__ a22,
           const float* __restrict__ g2, const float* __restrict__ b2,
           const float* __restrict__ m2, const float* __restrict__ v2,
           const float* __restrict__ Wl, const float* __restrict__ bl,
           float* __restrict__ out, int B)
{
    extern __shared__ float sm[];
    const int tid = threadIdx.x;

    // ---- stage weights into smem (swizzled layouts) ----
    // W1 quads: idx = (k2*32 + lw)*4 + t ; o = 2*lw + (t>>1), k = 2*k2 + (t&1)
    for (int i = tid; i < SZ_W1Q; i += NTHR) {
        int t = i & 3, lw = (i >> 2) & 31, k2 = i >> 7;
        int o = 2 * lw + (t >> 1), k = 2 * k2 + (t & 1);
        sm[OFF_W1Q + i] = (k < 125) ? Wt1[o * 125 + k] : 0.f;
    }
    // W2 quads: idx = (q*32 + lw)*4 + t ; o = lw, k = 4*q + t
    for (int i = tid; i < SZ_W2Q; i += NTHR) {
        int t = i & 3, lw = (i >> 2) & 31, q = i >> 7;
        sm[OFF_W2Q + i] = Wt2[lw * 64 + 4 * q + t];
    }
    // Wl transposed: Wls[idx*13 + c] = Wl[c*320 + idx]
    for (int i = tid; i < SZ_WLS; i += NTHR) {
        int ii = i / 13, c = i - ii * 13;
        sm[OFF_WLS + i] = Wl[c * 320 + ii];
    }
    if (tid < 64) { sm[OFF_A11 + tid] = a11[tid]; sm[OFF_A21 + tid] = a21[tid]; }
    if (tid < 32) { sm[OFF_A12 + tid] = a12[tid]; sm[OFF_A22 + tid] = a22[tid]; }
    if (tid < 5) {
        float s = g1[tid] * rsqrtf(v1[tid] + BN_EPS);
        sm[OFF_SC1 + tid] = s; sm[OFF_BI1 + tid] = b1[tid] - m1[tid] * s;
        float s2_ = g2[tid] * rsqrtf(v2[tid] + BN_EPS);
        sm[OFF_SC2 + tid] = s2_; sm[OFF_BI2 + tid] = b2[tid] - m2[tid] * s2_;
    }
    if (tid < 13) sm[OFF_BL + tid] = bl[tid];
    __syncthreads();

    const int w = tid >> 5, l = tid & 31;
    const int b = blockIdx.x * NW + w;
    if (b >= B) return;

    float* xw  = sm + OFF_WARP + w * PW;   // [2 paths][5 nodes][128 (125 + zero pad)]
    float* ysA = xw + 1280;                // BN1 output, path a: [5][64]
    float* ysN = ysA + 320;                // path n

    // ---- load x(b) into smem, split halves, zero-pad k to 128 ----
    {
        const float* xg = x + (size_t)b * 1250;
        #pragma unroll 8
        for (int it = 0; it < 40; ++it) {
            int i = it * 32 + l;
            int k = i & 127, pn = i >> 7;
            int p = (pn >= 5), n = pn - 5 * p;
            xw[i] = (k < 125) ? xg[n * 250 + p * 125 + k] : 0.f;
        }
    }
    __syncwarp();

    const float a11a = sm[OFF_A11 + 2 * l], a11b = sm[OFF_A11 + 2 * l + 1];
    const float a21a = sm[OFF_A21 + 2 * l], a21b = sm[OFF_A21 + 2 * l + 1];

    // =========== Layer 1: GraphAttn(125->64) + BN + ReLU, paths a and n ===========
    #pragma unroll
    for (int p = 0; p < 2; ++p) {
        // h[n][o] for o = 2l, 2l+1 ; accumulate in f32x2 pairs along k
        u64 acc0[5], acc1[5];
        #pragma unroll
        for (int n = 0; n < 5; ++n) { acc0[n] = 0ull; acc1[n] = 0ull; }
        const float4* xp4 = (const float4*)(xw + p * 640);
        const float4* W4  = (const float4*)(sm + OFF_W1Q);
        #pragma unroll 4
        for (int q = 0; q < 32; ++q) {          // 4 k per iter, zero-padded
            float4 xq[5];
            #pragma unroll
            for (int n = 0; n < 5; ++n) xq[n] = xp4[n * 32 + q];
            #pragma unroll
            for (int h2 = 0; h2 < 2; ++h2) {
                float4 wv = W4[(2 * q + h2) * 32 + l];
                u64 w0 = pk(wv.x, wv.y), w1 = pk(wv.z, wv.w);
                #pragma unroll
                for (int n = 0; n < 5; ++n) {
                    u64 xv = h2 ? pk(xq[n].z, xq[n].w) : pk(xq[n].x, xq[n].y);
                    fma2(acc0[n], xv, w0);
                    fma2(acc1[n], xv, w1);
                }
            }
        }
        float h12[2][5];
        #pragma unroll
        for (int n = 0; n < 5; ++n) {
            float2 t0 = upk(acc0[n]); h12[0][n] = t0.x + t0.y;
            float2 t1 = upk(acc1[n]); h12[1][n] = t1.x + t1.y;
        }
        // scores: s1 = h @ a11, s2 = h @ a21 (h1 == h2 in layer 1)
        float s1[5], s2[5];
        #pragma unroll
        for (int n = 0; n < 5; ++n) {
            s1[n] = wred(fmaf(h12[0][n], a11a, h12[1][n] * a11b));
            s2[n] = wred(fmaf(h12[0][n], a21a, h12[1][n] * a21b));
        }
        float o12[2][5];
        #pragma unroll
        for (int n = 0; n < 5; ++n) { o12[0][n] = 0.f; o12[1][n] = 0.f; }
        attn_apply<2>(s1, s2, h12, o12);
        // BN1 + ReLU -> smem
        float* ys = p ? ysN : ysA;
        #pragma unroll
        for (int n = 0; n < 5; ++n) {
            float sc = sm[OFF_SC1 + n], bi = sm[OFF_BI1 + n];
            float y0 = fmaxf(fmaf(o12[0][n], sc, bi), 0.f);
            float y1 = fmaxf(fmaf(o12[1][n], sc, bi), 0.f);
            *(float2*)(ys + n * 64 + 2 * l) = make_float2(y0, y1);
        }
    }
    __syncwarp();

    // =========== Layer 2: GraphAttn(64->32) x2 (cross paths) ===========
    // hA = bn(xa) @ W2^T, hN = bn(xn) @ W2^T ; o2 = l (one column per lane)
    u64 aAcc[5], aNcc[5];
    #pragma unroll
    for (int n = 0; n < 5; ++n) { aAcc[n] = 0ull; aNcc[n] = 0ull; }
    {
        const float4* W24 = (const float4*)(sm + OFF_W2Q);
        const float4* yA4 = (const float4*)ysA;
        const float4* yN4 = (const float4*)ysN;
        #pragma unroll 4
        for (int q = 0; q < 16; ++q) {
            float4 wv = W24[q * 32 + l];
            u64 w01 = pk(wv.x, wv.y), w23 = pk(wv.z, wv.w);
            #pragma unroll
            for (int n = 0; n < 5; ++n) {
                float4 xa4 = yA4[n * 16 + q];
                float4 xn4 = yN4[n * 16 + q];
                fma2(aAcc[n], pk(xa4.x, xa4.y), w01);
                fma2(aAcc[n], pk(xa4.z, xa4.w), w23);
                fma2(aNcc[n], pk(xn4.x, xn4.y), w01);
                fma2(aNcc[n], pk(xn4.z, xn4.w), w23);
            }
        }
    }
    float hA[1][5], hN[1][5];
    #pragma unroll
    for (int n = 0; n < 5; ++n) {
        float2 ta = upk(aAcc[n]); hA[0][n] = ta.x + ta.y;
        float2 tn = upk(aNcc[n]); hN[0][n] = tn.x + tn.y;
    }
    const float a12l = sm[OFF_A12 + l], a22l = sm[OFF_A22 + l];
    float s1a[5], s2a[5], s1b[5], s2b[5];
    #pragma unroll
    for (int n = 0; n < 5; ++n) {
        s1a[n] = wred(hA[0][n] * a12l);   // ya: h1 = hA
        s2a[n] = wred(hN[0][n] * a22l);
        s1b[n] = wred(hN[0][n] * a12l);   // yn: h1 = hN
        s2b[n] = wred(hA[0][n] * a22l);
    }
    float oA[1][5], oN[1][5];
    #pragma unroll
    for (int n = 0; n < 5; ++n) { oA[0][n] = 0.f; oN[0][n] = 0.f; }
    attn_apply<1>(s1a, s2a, hA, oA);
    attn_apply<1>(s1b, s2b, hN, oN);
    // BN2 + ReLU
    float fa[5], fb[5];
    #pragma unroll
    for (int n = 0; n < 5; ++n) {
        float sc = sm[OFF_SC2 + n], bi = sm[OFF_BI2 + n];
        fa[n] = fmaxf(fmaf(oA[0][n], sc, bi), 0.f);
        fb[n] = fmaxf(fmaf(oN[0][n], sc, bi), 0.f);
    }

    // =========== final Linear(320 -> 13) ===========
    // feat[n*64 + f]: f<32 from ya (lane l holds f=l), f>=32 from yn
    float acc13[13];
    #pragma unroll
    for (int c = 0; c < 13; ++c) acc13[c] = 0.f;
    #pragma unroll
    for (int n = 0; n < 5; ++n) {
        const float* wA = sm + OFF_WLS + (n * 64 + l) * 13;
        const float* wB = sm + OFF_WLS + (n * 64 + 32 + l) * 13;
        #pragma unroll
        for (int c = 0; c < 13; ++c)
            acc13[c] += fa[n] * wA[c] + fb[n] * wB[c];
    }
    #pragma unroll
    for (int c = 0; c < 13; ++c) acc13[c] = wred(acc13[c]);
    if (l < 13) {
        float outv = 0.f;
        #pragma unroll
        for (int c = 0; c < 13; ++c) if (l == c) outv = acc13[c];
        out[(size_t)b * 13 + l] = outv + sm[OFF_BL + l];
    }
}

extern "C" void kernel_launch(void* const* d_in, const int* in_sizes, int n_in,
                              void* d_out, int out_size)
{
    const float* x   = (const float*)d_in[0];
    const float* Wt1 = (const float*)d_in[1];
    const float* a11 = (const float*)d_in[2];
    const float* a21 = (const float*)d_in[3];
    const float* g1  = (const float*)d_in[4];
    const float* b1  = (const float*)d_in[5];
    const float* m1  = (const float*)d_in[6];
    const float* v1  = (const float*)d_in[7];
    const float* Wt2 = (const float*)d_in[8];
    const float* a12 = (const float*)d_in[9];
    const float* a22 = (const float*)d_in[10];
    const float* g2  = (const float*)d_in[11];
    const float* b2  = (const float*)d_in[12];
    const float* m2  = (const float*)d_in[13];
    const float* v2  = (const float*)d_in[14];
    const float* Wl  = (const float*)d_in[15];
    const float* bl  = (const float*)d_in[16];

    int B = in_sizes[0] / 1250;
    int grid = (B + NW - 1) / NW;
    cudaFuncSetAttribute(gat_kernel, cudaFuncAttributeMaxDynamicSharedMemorySize, SMEM_BYTES);
    gat_kernel<<<grid, NTHR, SMEM_BYTES>>>(x, Wt1, a11, a21, g1, b1, m1, v1,
                                           Wt2, a12, a22, g2, b2, m2, v2, Wl, bl,
                                           (float*)d_out, B);
}

// round 2
// speedup vs baseline: 1.0013x; 1.0013x over previous
#include <cuda_runtime.h>

#define NW 16               // warps (= batches) per CTA
#define NTHR 512
#define ALPHA 0.2f
#define BN_EPS 1e-5f

// ---- shared memory layout (float offsets) ----
#define OFF_W1Q 0
#define SZ_W1Q  8192        // 64 k-pairs x 32 lanes x 4 (zero-padded k>=125)
#define OFF_W2Q (OFF_W1Q + SZ_W1Q)      // 8192
#define SZ_W2Q  2048        // 16 quads x 32 lanes x 4
#define OFF_WLS (OFF_W2Q + SZ_W2Q)      // 10240
#define SZ_WLS  4160        // [320][13] transposed
#define OFF_A11 (OFF_WLS + SZ_WLS)      // 14400
#define OFF_A21 (OFF_A11 + 64)          // 14464
#define OFF_A12 (OFF_A21 + 64)          // 14528
#define OFF_A22 (OFF_A12 + 32)          // 14560
#define OFF_SC1 (OFF_A22 + 32)          // 14592
#define OFF_BI1 (OFF_SC1 + 5)
#define OFF_SC2 (OFF_BI1 + 5)
#define OFF_BI2 (OFF_SC2 + 5)
#define OFF_BL  (OFF_BI2 + 5)           // 14612 (13)
#define OFF_WARP 14628                  // 16B aligned
#define PW 1920                         // per-warp: xs 2*5*128 + ysA 320 + ysN 320
#define SMEM_FLOATS (OFF_WARP + NW * PW)
#define SMEM_BYTES (SMEM_FLOATS * 4)    // 181392 B

typedef unsigned long long u64;

__device__ __forceinline__ u64 pk(float a, float b) {
    u64 r; asm("mov.b64 %0, {%1, %2};" : "=l"(r) : "f"(a), "f"(b)); return r;
}
__device__ __forceinline__ float2 upk(u64 v) {
    float2 r; asm("mov.b64 {%0, %1}, %2;" : "=f"(r.x), "=f"(r.y) : "l"(v)); return r;
}
// packed fp32x2 FMA (Blackwell f32x2 pipe): d = a*b + d, two lanes per reg-pair
__device__ __forceinline__ void fma2(u64& d, u64 a, u64 b) {
    asm("fma.rn.f32x2 %0, %1, %2, %3;" : "=l"(d) : "l"(a), "l"(b), "l"(d));
}
__device__ __forceinline__ float wred(float v) {
    #pragma unroll
    for (int s = 16; s > 0; s >>= 1) v += __shfl_xor_sync(0xffffffffu, v, s);
    return v;
}

// e[i][j] = lrelu(s1[i] + s2[j]); attn = softmax over i (axis=1);
// o[c][i] += sum_j attn[i][j] * h[c][j]
template <int C>
__device__ __forceinline__ void attn_apply(const float s1[5], const float s2[5],
                                           const float (&h)[C][5], float (&o)[C][5]) {
    #pragma unroll
    for (int j = 0; j < 5; ++j) {
        float e[5]; float m = -1e30f;
        #pragma unroll
        for (int i = 0; i < 5; ++i) {
            float v = s1[i] + s2[j];
            v = v > 0.f ? v : ALPHA * v;
            e[i] = v; m = fmaxf(m, v);
        }
        float Z = 0.f;
        #pragma unroll
        for (int i = 0; i < 5; ++i) { e[i] = __expf(e[i] - m); Z += e[i]; }
        float r = __fdividef(1.f, Z);
        #pragma unroll
        for (int i = 0; i < 5; ++i) {
            float wv = e[i] * r;
            #pragma unroll
            for (int c = 0; c < C; ++c) o[c][i] = fmaf(wv, h[c][j], o[c][i]);
        }
    }
}

__global__ void __launch_bounds__(NTHR, 1)
gat_kernel(const float* __restrict__ x,
           const float* __restrict__ Wt1, const float* __restrict__ a11, const float* __restrict__ a21,
           const float* __restrict__ g1, const float* __restrict__ b1,
           const float* __restrict__ m1, const float* __restrict__ v1,
           const float* __restrict__ Wt2, const float* __restrict__ a12, const float* __restrict__ a22,
           const float* __restrict__ g2, const float* __restrict__ b2,
           const float* __restrict__ m2, const float* __restrict__ v2,
           const float* __restrict__ Wl, const float* __restrict__ bl,
           float* __restrict__ out, int B)
{
    extern __shared__ float sm[];
    const int tid = threadIdx.x;

    // ---- stage weights into smem (swizzled layouts) ----
    // W1 quads: idx = (k2*32 + lw)*4 + t ; o = 2*lw + (t>>1), k = 2*k2 + (t&1)
    for (int i = tid; i < SZ_W1Q; i += NTHR) {
        int t = i & 3, lw = (i >> 2) & 31, k2 = i >> 7;
        int o = 2 * lw + (t >> 1), k = 2 * k2 + (t & 1);
        sm[OFF_W1Q + i] = (k < 125) ? Wt1[o * 125 + k] : 0.f;
    }
    // W2 quads: idx = (q*32 + lw)*4 + t ; o = lw, k = 4*q + t
    for (int i = tid; i < SZ_W2Q; i += NTHR) {
        int t = i & 3, lw = (i >> 2) & 31, q = i >> 7;
        sm[OFF_W2Q + i] = Wt2[lw * 64 + 4 * q + t];
    }
    // Wl transposed: Wls[idx*13 + c] = Wl[c*320 + idx]
    for (int i = tid; i < SZ_WLS; i += NTHR) {
        int ii = i / 13, c = i - ii * 13;
        sm[OFF_WLS + i] = Wl[c * 320 + ii];
    }
    if (tid < 64) { sm[OFF_A11 + tid] = a11[tid]; sm[OFF_A21 + tid] = a21[tid]; }
    if (tid < 32) { sm[OFF_A12 + tid] = a12[tid]; sm[OFF_A22 + tid] = a22[tid]; }
    if (tid < 5) {
        float s = g1[tid] * rsqrtf(v1[tid] + BN_EPS);
        sm[OFF_SC1 + tid] = s; sm[OFF_BI1 + tid] = b1[tid] - m1[tid] * s;
        float s2_ = g2[tid] * rsqrtf(v2[tid] + BN_EPS);
        sm[OFF_SC2 + tid] = s2_; sm[OFF_BI2 + tid] = b2[tid] - m2[tid] * s2_;
    }
    if (tid < 13) sm[OFF_BL + tid] = bl[tid];
    __syncthreads();

    const int w = tid >> 5, l = tid & 31;
    const int b = blockIdx.x * NW + w;
    if (b >= B) return;

    float* xw  = sm + OFF_WARP + w * PW;   // [2 paths][5 nodes][128 (125 + zero pad)]
    float* ysA = xw + 1280;                // BN1 output, path a: [5][64]
    float* ysN = ysA + 320;                // path n

    // ---- load x(b) into smem, split halves, zero-pad k to 128 ----
    {
        const float* xg = x + (size_t)b * 1250;
        #pragma unroll 8
        for (int it = 0; it < 40; ++it) {
            int i = it * 32 + l;
            int k = i & 127, pn = i >> 7;
            int p = (pn >= 5), n = pn - 5 * p;
            xw[i] = (k < 125) ? xg[n * 250 + p * 125 + k] : 0.f;
        }
    }
    __syncwarp();

    const float a11a = sm[OFF_A11 + 2 * l], a11b = sm[OFF_A11 + 2 * l + 1];
    const float a21a = sm[OFF_A21 + 2 * l], a21b = sm[OFF_A21 + 2 * l + 1];

    // =========== Layer 1: GraphAttn(125->64) + BN + ReLU, paths a and n ===========
    #pragma unroll
    for (int p = 0; p < 2; ++p) {
        // h[n][o] for o = 2l, 2l+1 ; accumulate in f32x2 pairs along k
        u64 acc0[5], acc1[5];
        #pragma unroll
        for (int n = 0; n < 5; ++n) { acc0[n] = 0ull; acc1[n] = 0ull; }
        const float4* xp4 = (const float4*)(xw + p * 640);
        const float4* W4  = (const float4*)(sm + OFF_W1Q);
        #pragma unroll 4
        for (int q = 0; q < 32; ++q) {          // 4 k per iter, zero-padded
            float4 xq[5];
            #pragma unroll
            for (int n = 0; n < 5; ++n) xq[n] = xp4[n * 32 + q];
            #pragma unroll
            for (int h2 = 0; h2 < 2; ++h2) {
                float4 wv = W4[(2 * q + h2) * 32 + l];
                u64 w0 = pk(wv.x, wv.y), w1 = pk(wv.z, wv.w);
                #pragma unroll
                for (int n = 0; n < 5; ++n) {
                    u64 xv = h2 ? pk(xq[n].z, xq[n].w) : pk(xq[n].x, xq[n].y);
                    fma2(acc0[n], xv, w0);
                    fma2(acc1[n], xv, w1);
                }
            }
        }
        float h12[2][5];
        #pragma unroll
        for (int n = 0; n < 5; ++n) {
            float2 t0 = upk(acc0[n]); h12[0][n] = t0.x + t0.y;
            float2 t1 = upk(acc1[n]); h12[1][n] = t1.x + t1.y;
        }
        // scores: s1 = h @ a11, s2 = h @ a21 (h1 == h2 in layer 1)
        float s1[5], s2[5];
        #pragma unroll
        for (int n = 0; n < 5; ++n) {
            s1[n] = wred(fmaf(h12[0][n], a11a, h12[1][n] * a11b));
            s2[n] = wred(fmaf(h12[0][n], a21a, h12[1][n] * a21b));
        }
        float o12[2][5];
        #pragma unroll
        for (int n = 0; n < 5; ++n) { o12[0][n] = 0.f; o12[1][n] = 0.f; }
        attn_apply<2>(s1, s2, h12, o12);
        // BN1 + ReLU -> smem
        float* ys = p ? ysN : ysA;
        #pragma unroll
        for (int n = 0; n < 5; ++n) {
            float sc = sm[OFF_SC1 + n], bi = sm[OFF_BI1 + n];
            float y0 = fmaxf(fmaf(o12[0][n], sc, bi), 0.f);
            float y1 = fmaxf(fmaf(o12[1][n], sc, bi), 0.f);
            *(float2*)(ys + n * 64 + 2 * l) = make_float2(y0, y1);
        }
    }
    __syncwarp();

    // =========== Layer 2: GraphAttn(64->32) x2 (cross paths) ===========
    // hA = bn(xa) @ W2^T, hN = bn(xn) @ W2^T ; o2 = l (one column per lane)
    u64 aAcc[5], aNcc[5];
    #pragma unroll
    for (int n = 0; n < 5; ++n) { aAcc[n] = 0ull; aNcc[n] = 0ull; }
    {
        const float4* W24 = (const float4*)(sm + OFF_W2Q);
        const float4* yA4 = (const float4*)ysA;
        const float4* yN4 = (const float4*)ysN;
        #pragma unroll 4
        for (int q = 0; q < 16; ++q) {
            float4 wv = W24[q * 32 + l];
            u64 w01 = pk(wv.x, wv.y), w23 = pk(wv.z, wv.w);
            #pragma unroll
            for (int n = 0; n < 5; ++n) {
                float4 xa4 = yA4[n * 16 + q];
                float4 xn4 = yN4[n * 16 + q];
                fma2(aAcc[n], pk(xa4.x, xa4.y), w01);
                fma2(aAcc[n], pk(xa4.z, xa4.w), w23);
                fma2(aNcc[n], pk(xn4.x, xn4.y), w01);
                fma2(aNcc[n], pk(xn4.z, xn4.w), w23);
            }
        }
    }
    float hA[1][5], hN[1][5];
    #pragma unroll
    for (int n = 0; n < 5; ++n) {
        float2 ta = upk(aAcc[n]); hA[0][n] = ta.x + ta.y;
        float2 tn = upk(aNcc[n]); hN[0][n] = tn.x + tn.y;
    }
    const float a12l = sm[OFF_A12 + l], a22l = sm[OFF_A22 + l];
    float s1a[5], s2a[5], s1b[5], s2b[5];
    #pragma unroll
    for (int n = 0; n < 5; ++n) {
        s1a[n] = wred(hA[0][n] * a12l);   // ya: h1 = hA
        s2a[n] = wred(hN[0][n] * a22l);
        s1b[n] = wred(hN[0][n] * a12l);   // yn: h1 = hN
        s2b[n] = wred(hA[0][n] * a22l);
    }
    float oA[1][5], oN[1][5];
    #pragma unroll
    for (int n = 0; n < 5; ++n) { oA[0][n] = 0.f; oN[0][n] = 0.f; }
    attn_apply<1>(s1a, s2a, hA, oA);
    attn_apply<1>(s1b, s2b, hN, oN);
    // BN2 + ReLU
    float fa[5], fb[5];
    #pragma unroll
    for (int n = 0; n < 5; ++n) {
        float sc = sm[OFF_SC2 + n], bi = sm[OFF_BI2 + n];
        fa[n] = fmaxf(fmaf(oA[0][n], sc, bi), 0.f);
        fb[n] = fmaxf(fmaf(oN[0][n], sc, bi), 0.f);
    }

    // =========== final Linear(320 -> 13) ===========
    // feat[n*64 + f]: f<32 from ya (lane l holds f=l), f>=32 from yn
    float acc13[13];
    #pragma unroll
    for (int c = 0; c < 13; ++c) acc13[c] = 0.f;
    #pragma unroll
    for (int n = 0; n < 5; ++n) {
        const float* wA = sm + OFF_WLS + (n * 64 + l) * 13;
        const float* wB = sm + OFF_WLS + (n * 64 + 32 + l) * 13;
        #pragma unroll
        for (int c = 0; c < 13; ++c)
            acc13[c] += fa[n] * wA[c] + fb[n] * wB[c];
    }
    #pragma unroll
    for (int c = 0; c < 13; ++c) acc13[c] = wred(acc13[c]);
    if (l < 13) {
        float outv = 0.f;
        #pragma unroll
        for (int c = 0; c < 13; ++c) if (l == c) outv = acc13[c];
        out[(size_t)b * 13 + l] = outv + sm[OFF_BL + l];
    }
}

extern "C" void kernel_launch(void* const* d_in, const int* in_sizes, int n_in,
                              void* d_out, int out_size)
{
    const float* x   = (const float*)d_in[0];
    const float* Wt1 = (const float*)d_in[1];
    const float* a11 = (const float*)d_in[2];
    const float* a21 = (const float*)d_in[3];
    const float* g1  = (const float*)d_in[4];
    const float* b1  = (const float*)d_in[5];
    const float* m1  = (const float*)d_in[6];
    const float* v1  = (const float*)d_in[7];
    const float* Wt2 = (const float*)d_in[8];
    const float* a12 = (const float*)d_in[9];
    const float* a22 = (const float*)d_in[10];
    const float* g2  = (const float*)d_in[11];
    const float* b2  = (const float*)d_in[12];
    const float* m2  = (const float*)d_in[13];
    const float* v2  = (const float*)d_in[14];
    const float* Wl  = (const float*)d_in[15];
    const float* bl  = (const float*)d_in[16];

    int B = in_sizes[0] / 1250;
    int grid = (B + NW - 1) / NW;
    cudaFuncSetAttribute(gat_kernel, cudaFuncAttributeMaxDynamicSharedMemorySize, SMEM_BYTES);
    gat_kernel<<<grid, NTHR, SMEM_BYTES>>>(x, Wt1, a11, a21, g1, b1, m1, v1,
                                           Wt2, a12, a22, g2, b2, m2, v2, Wl, bl,
                                           (float*)d_out, B);
}